// round 6
// baseline (speedup 1.0000x reference)
#include <cuda_runtime.h>
#include <cuda_fp16.h>
#include <math.h>

#define NN 2000
#define TT 64
#define HH 64
#define KK 10
#define PD 32
#define EF 32000
#define EK (NN*KK)
#define EE (EF+EK)
#define RPB 8     // topk rows per block

// ---------------- scratch (static __device__, no allocation) ----------------
__device__ float g_e[NN*PD];          // normalized embeddings
__device__ int   g_knn_dst[EK];
__device__ float g_knn_w[EK];         // vals * alpha
__device__ int   g_deg[NN];
__device__ int   g_rowstart[NN+1];
__device__ int   g_cursor[NN];
__device__ int   g_csr_src[EE];
__device__ float g_csr_w[EE];
__device__ __half g_yh[(size_t)NN*TT*HH];  // xt @ Wmsg^T + b, fp16 (16MB, L2-resident)
__device__ float g_p[NN*TT];          // xt . att_src + b
__device__ float g_q[NN*TT];          // xt . att_dst + b

// ---------------- packed f32x2 helpers ----------------
__device__ __forceinline__ void ffma2(unsigned long long& d, unsigned long long a, unsigned long long b) {
    asm("fma.rn.f32x2 %0, %1, %2, %0;" : "+l"(d) : "l"(a), "l"(b));
}
__device__ __forceinline__ float upk_sum(unsigned long long v) {
    float lo, hi;
    asm("mov.b64 {%0,%1}, %2;" : "=f"(lo), "=f"(hi) : "l"(v));
    return lo + hi;
}

// ---------------- K1: x_agg -> e (normalized) ----------------
__global__ void k_embed(const float* __restrict__ x, const float* __restrict__ npw) {
    int n = blockIdx.x; int h = threadIdx.x;      // 64 threads
    __shared__ float xa[HH];
    __shared__ float ev[PD];
    const float* xp = x + (size_t)n*TT*HH + h;
    float s = 0.f;
    #pragma unroll
    for (int t = 0; t < TT; t++) s += xp[t*HH];
    xa[h] = s * (1.0f/TT);
    __syncthreads();
    if (h < PD) {
        float acc = 0.f;
        #pragma unroll
        for (int c = 0; c < HH; c++) acc += xa[c] * npw[h*HH + c];
        ev[h] = acc;
    }
    __syncthreads();
    if (h < PD) {
        float v = ev[h];
        float ss = v*v;
        #pragma unroll
        for (int o = 16; o > 0; o >>= 1) ss += __shfl_xor_sync(0xffffffffu, ss, o);
        float nrm = fmaxf(sqrtf(ss), 1e-12f);
        g_e[n*PD + h] = v / nrm;
    }
}

// ---------------- K2: 8 rows per block, warp-per-row top-(K+1) ----------------
#define TK_SM_FLOATS (RPB*NN + RPB*PD)
#define TK_SM_BYTES  (TK_SM_FLOATS*4)
__global__ void __launch_bounds__(256) k_topk(const float* __restrict__ mix_logit) {
    extern __shared__ float smt[];
    float* sim = smt;
    float* ei  = smt + RPB*NN;
    int i0 = blockIdx.x * RPB;
    int tid = threadIdx.x;

    for (int idx = tid; idx < RPB*PD; idx += 256) ei[idx] = g_e[i0*PD + idx];
    __syncthreads();

    for (int j = tid; j < NN; j += 256) {
        const float4* ej = (const float4*)(g_e + j*PD);
        float4 ev[8];
        #pragma unroll
        for (int c = 0; c < 8; c++) ev[c] = ej[c];
        #pragma unroll
        for (int r = 0; r < RPB; r++) {
            const float4* er = (const float4*)(ei + r*PD);
            float dsum = 0.f;
            #pragma unroll
            for (int c = 0; c < 8; c++) {
                float4 e4 = er[c];
                dsum += ev[c].x*e4.x + ev[c].y*e4.y + ev[c].z*e4.z + ev[c].w*e4.w;
            }
            sim[r*NN + j] = dsum;
        }
    }
    __syncthreads();

    float alpha = 1.f/(1.f + expf(-mix_logit[0]));
    int w = tid >> 5, lane = tid & 31;
    int i = i0 + w;
    float* simr = sim + w*NN;
    for (int k = 0; k <= KK; k++) {
        float bv = -INFINITY; int bi = NN;
        for (int j = lane; j < NN; j += 32) {
            float v = simr[j];
            if (v > bv || (v == bv && j < bi)) { bv = v; bi = j; }
        }
        #pragma unroll
        for (int off = 16; off > 0; off >>= 1) {
            float ov = __shfl_down_sync(0xffffffffu, bv, off);
            int   oi = __shfl_down_sync(0xffffffffu, bi, off);
            if (ov > bv || (ov == bv && oi < bi)) { bv = ov; bi = oi; }
        }
        bi = __shfl_sync(0xffffffffu, bi, 0);
        bv = __shfl_sync(0xffffffffu, bv, 0);
        if (lane == 0) {
            if (k > 0) { g_knn_dst[i*KK + (k-1)] = bi; g_knn_w[i*KK + (k-1)] = bv*alpha; }
            simr[bi] = -INFINITY;
        }
        __syncwarp();
    }
}

// ---------------- CSR build ----------------
__global__ void k_zero_deg() {
    int i = blockIdx.x*blockDim.x + threadIdx.x;
    if (i < NN) g_deg[i] = 0;
}

__global__ void k_deg(const int* __restrict__ fei) {
    int e = blockIdx.x*blockDim.x + threadIdx.x;
    if (e >= EE) return;
    int d = (e < EF) ? fei[EF + e] : g_knn_dst[e - EF];
    atomicAdd(&g_deg[d], 1);
}

__global__ void k_scan() {                         // 1 block, 1024 threads
    __shared__ int a[2048], b[2048];
    int tid = threadIdx.x;
    for (int i = tid; i < 2048; i += 1024) a[i] = (i < NN) ? g_deg[i] : 0;
    __syncthreads();
    int* in = a; int* out = b;
    for (int off = 1; off < 2048; off <<= 1) {
        for (int i = tid; i < 2048; i += 1024)
            out[i] = in[i] + (i >= off ? in[i-off] : 0);
        __syncthreads();
        int* t = in; in = out; out = t;
    }
    for (int i = tid; i <= NN; i += 1024) {
        int rs = (i == 0) ? 0 : in[i-1];
        g_rowstart[i] = rs;
        if (i < NN) g_cursor[i] = rs;
    }
}

__global__ void k_scatter(const int* __restrict__ fei, const float* __restrict__ fea,
                          const float* __restrict__ mix_logit) {
    int e = blockIdx.x*blockDim.x + threadIdx.x;
    if (e >= EE) return;
    float alpha = 1.f/(1.f + expf(-mix_logit[0]));
    int s, d; float w;
    if (e < EF) { s = fei[e]; d = fei[EF + e]; w = fea[e]*(1.f - alpha); }
    else { int ke = e - EF; s = ke / KK; d = g_knn_dst[ke]; w = g_knn_w[ke]; }
    int pos = atomicAdd(&g_cursor[d], 1);
    g_csr_src[pos] = s; g_csr_w[pos] = w;
}

// ---------------- K3: fused tconv -> (y, p, q) + self term ----------------
// 8tt x 2o register tiling for GEMMs; conv channel-pass-outer (low reg pressure).
// smem (floats): xs 4224 | xts 4096 | wp 4160  -> 49920 B, 4 blocks/SM @ 64 regs
#define XS_OFF   0
#define XTS_OFF  ((TT+2)*HH)
#define WP_OFF   (XTS_OFF + TT*HH)
#define SM_FLOATS (WP_OFF + 4160)
#define SM_BYTES  (SM_FLOATS*4)

__global__ void __launch_bounds__(256, 4) k_node(
    const float* __restrict__ x,
    const float* __restrict__ tw,  const float* __restrict__ tb,
    const float* __restrict__ lmw, const float* __restrict__ lmb,
    const float* __restrict__ lsw, const float* __restrict__ lsb,
    const float* __restrict__ asw, const float* __restrict__ asb,
    const float* __restrict__ adw, const float* __restrict__ adb,
    float* __restrict__ out)
{
    extern __shared__ float sm[];
    float* xs  = sm + XS_OFF;
    float* xts = sm + XTS_OFF;
    float* wpf = sm + WP_OFF;
    float2* wp2 = (float2*)wpf;
    unsigned long long* wpu = (unsigned long long*)wpf;
    const ulonglong2* xsu  = (const ulonglong2*)xs;
    const ulonglong2* xtsu = (const ulonglong2*)xts;

    int n = blockIdx.x;
    int tid = threadIdx.x;
    int o = tid & 31;            // channels o and o+32
    int tc = tid >> 5;           // 8 row-slices
    int base = tc * 8;

    // phase 1: load x (halo) + stage lsw packed: wp2[ip*65+oc] = (w[oc,2ip], w[oc,2ip+1])
    const float* xn = x + (size_t)n*TT*HH;
    for (int idx = tid; idx < TT*HH; idx += 256) xs[idx + HH] = xn[idx];
    for (int idx = tid; idx < HH; idx += 256) { xs[idx] = 0.f; xs[(TT+1)*HH + idx] = 0.f; }
    {
        const float2* w2 = (const float2*)lsw;   // [oc][32] float2, coalesced
        #pragma unroll
        for (int it = 0; it < 8; it++) {
            int idx = it*256 + tid;              // [0, 2048)
            int oc = idx >> 5, ip = idx & 31;
            wp2[ip*65 + oc] = w2[idx];
        }
    }
    __syncthreads();

    // phase 2: self term -> out : x @ Wself^T + b  (2 channels x 8 rows)
    {
        unsigned long long aA[8], aB[8];
        #pragma unroll
        for (int tt = 0; tt < 8; tt++) { aA[tt] = 0ULL; aB[tt] = 0ULL; }
        #pragma unroll 4
        for (int ip2 = 0; ip2 < 16; ip2++) {
            unsigned long long wA0 = wpu[(2*ip2)*65 + o];
            unsigned long long wB0 = wpu[(2*ip2)*65 + o + 32];
            unsigned long long wA1 = wpu[(2*ip2+1)*65 + o];
            unsigned long long wB1 = wpu[(2*ip2+1)*65 + o + 32];
            #pragma unroll
            for (int tt = 0; tt < 8; tt++) {
                ulonglong2 xv = xsu[(base+tt+1)*16 + ip2];
                ffma2(aA[tt], xv.x, wA0); ffma2(aA[tt], xv.y, wA1);
                ffma2(aB[tt], xv.x, wB0); ffma2(aB[tt], xv.y, wB1);
            }
        }
        float* op = out + (size_t)n*TT*HH;
        float sbA = lsb[o], sbB = lsb[o+32];
        #pragma unroll
        for (int tt = 0; tt < 8; tt++) {
            op[(base+tt)*HH + o]      = upk_sum(aA[tt]) + sbA;
            op[(base+tt)*HH + o + 32] = upk_sum(aB[tt]) + sbB;
        }
    }

    // phases 3-4: temporal conv, channel-pass OUTER (low live regs), 4 i-quarters
    for (int cpass = 0; cpass < 2; cpass++) {
        int oc = o + cpass*32;
        unsigned long long ac[8];
        #pragma unroll
        for (int tt = 0; tt < 8; tt++) ac[tt] = 0ULL;
        for (int h = 0; h < 4; h++) {
            __syncthreads();
            // stage quarter: i-global in [h*16,h*16+16): wp[(k*8+ip)*65+ch] packed pair
            #pragma unroll
            for (int it = 0; it < 12; it++) {
                int idx = it*256 + tid;              // [0, 3072)
                int ch = idx / 48, j = idx - ch*48;  // j = il*3 + k, il<16
                int il = j / 3, k = j - il*3;
                int ip = il >> 1, comp = il & 1;
                wpf[((k*8 + ip)*65 + ch)*2 + comp] = tw[ch*192 + h*48 + j];
            }
            __syncthreads();
            #pragma unroll
            for (int g = 0; g < 4; g++) {
                int lp0 = 2*g, lp1 = 2*g + 1;
                unsigned long long w00 = wpu[(0*8+lp0)*65 + oc], w01 = wpu[(0*8+lp1)*65 + oc];
                unsigned long long w10 = wpu[(1*8+lp0)*65 + oc], w11 = wpu[(1*8+lp1)*65 + oc];
                unsigned long long w20 = wpu[(2*8+lp0)*65 + oc], w21 = wpu[(2*8+lp1)*65 + oc];
                int ig = h*4 + g;
                ulonglong2 r0 = xsu[(base+0)*16 + ig];
                ulonglong2 r1 = xsu[(base+1)*16 + ig];
                #pragma unroll
                for (int tt = 0; tt < 8; tt++) {
                    ulonglong2 r2 = xsu[(base+tt+2)*16 + ig];
                    ffma2(ac[tt], r0.x, w00); ffma2(ac[tt], r0.y, w01);
                    ffma2(ac[tt], r1.x, w10); ffma2(ac[tt], r1.y, w11);
                    ffma2(ac[tt], r2.x, w20); ffma2(ac[tt], r2.y, w21);
                    r0 = r1; r1 = r2;
                }
            }
        }
        float bo = tb[oc];
        #pragma unroll
        for (int tt = 0; tt < 8; tt++) xts[(base+tt)*HH + oc] = upk_sum(ac[tt]) + bo;
    }
    __syncthreads();

    // phase 5: stage lmw packed
    {
        const float2* w2 = (const float2*)lmw;
        #pragma unroll
        for (int it = 0; it < 8; it++) {
            int idx = it*256 + tid;
            int oc = idx >> 5, ip = idx & 31;
            wp2[ip*65 + oc] = w2[idx];
        }
    }
    __syncthreads();

    // phase 6: y = xt @ Wmsg^T + b -> g_yh (fp16)
    {
        unsigned long long aA[8], aB[8];
        #pragma unroll
        for (int tt = 0; tt < 8; tt++) { aA[tt] = 0ULL; aB[tt] = 0ULL; }
        #pragma unroll 4
        for (int ip2 = 0; ip2 < 16; ip2++) {
            unsigned long long wA0 = wpu[(2*ip2)*65 + o];
            unsigned long long wB0 = wpu[(2*ip2)*65 + o + 32];
            unsigned long long wA1 = wpu[(2*ip2+1)*65 + o];
            unsigned long long wB1 = wpu[(2*ip2+1)*65 + o + 32];
            #pragma unroll
            for (int tt = 0; tt < 8; tt++) {
                ulonglong2 xv = xtsu[(base+tt)*16 + ip2];
                ffma2(aA[tt], xv.x, wA0); ffma2(aA[tt], xv.y, wA1);
                ffma2(aB[tt], xv.x, wB0); ffma2(aB[tt], xv.y, wB1);
            }
        }
        __half* yp = g_yh + (size_t)n*TT*HH;
        float ybA = lmb[o], ybB = lmb[o+32];
        #pragma unroll
        for (int tt = 0; tt < 8; tt++) {
            yp[(base+tt)*HH + o]      = __float2half_rn(upk_sum(aA[tt]) + ybA);
            yp[(base+tt)*HH + o + 32] = __float2half_rn(upk_sum(aB[tt]) + ybB);
        }
    }

    // phase 7: p, q reductions over xts
    int warp = tid >> 5, lane = tid & 31;
    float asb0 = asb[0], adb0 = adb[0];
    float aw1 = asw[lane], aw2 = asw[lane+32];
    float dw1 = adw[lane], dw2 = adw[lane+32];
    for (int tt = 0; tt < 8; tt++) {
        int t = warp*8 + tt;
        float v1 = xts[t*HH + lane], v2 = xts[t*HH + lane + 32];
        float pp = v1*aw1 + v2*aw2;
        float qq = v1*dw1 + v2*dw2;
        #pragma unroll
        for (int off = 16; off > 0; off >>= 1) {
            pp += __shfl_down_sync(0xffffffffu, pp, off);
            qq += __shfl_down_sync(0xffffffffu, qq, off);
        }
        if (lane == 0) { g_p[n*TT + t] = pp + asb0; g_q[n*TT + t] = qq + adb0; }
    }
}

// ---------------- K4: per-dst softmax + aggregation (fp16 y gather) ----------------
#define CH 16
__global__ void __launch_bounds__(256) k_aggr(float* __restrict__ out) {
    __shared__ float coefw[CH*TT];
    __shared__ int   srcs[CH];
    __shared__ float ws[CH];
    __shared__ float qv[TT];
    __shared__ float ms[TT];
    __shared__ float mpart[4*TT];
    __shared__ float zpart[4*TT];
    __shared__ float zinv[TT];

    int d = blockIdx.x, tid = threadIdx.x;
    int t = tid & 63, q = tid >> 6;
    int r0 = g_rowstart[d], r1 = g_rowstart[d+1];
    int deg = r1 - r0;
    if (tid < TT) qv[tid] = g_q[d*TT + tid];
    __syncthreads();
    float qvt = qv[t];

    float m = -INFINITY;
    for (int e = r0 + q; e < r1; e += 4) {
        int s = g_csr_src[e];
        float a = g_p[s*TT + t] + qvt;
        a = a > 0.f ? a : 0.2f*a;
        m = fmaxf(m, a);
    }
    mpart[q*TT + t] = m;
    __syncthreads();
    if (tid < TT) {
        ms[t] = fmaxf(fmaxf(mpart[t], mpart[TT+t]), fmaxf(mpart[2*TT+t], mpart[3*TT+t]));
    }
    __syncthreads();
    float mt = ms[t];

    float a0[8], a1[8];
    #pragma unroll
    for (int j = 0; j < 8; j++) { a0[j] = 0.f; a1[j] = 0.f; }
    float zloc = 0.f;
    int t0 = tid >> 3;
    const uint4* Y = (const uint4*)g_yh;

    for (int c0 = r0; c0 < r1; c0 += CH) {
        int cn = min(CH, r1 - c0);
        if (tid < cn) { srcs[tid] = g_csr_src[c0+tid]; ws[tid] = g_csr_w[c0+tid]; }
        __syncthreads();
        #pragma unroll
        for (int k = 0; k < 4; k++) {
            int ee = q + 4*k;
            if (ee < cn) {
                int s = srcs[ee];
                float a = g_p[s*TT + t] + qvt;
                a = a > 0.f ? a : 0.2f*a;
                float cc = __expf(a - mt);
                zloc += cc;
                coefw[ee*TT + t] = cc * ws[ee];
            }
        }
        __syncthreads();
        // register accumulation, 2 edges in flight
        int ee = 0;
        for (; ee + 1 < cn; ee += 2) {
            const uint4* ysA = Y + (size_t)srcs[ee]*512;
            const uint4* ysB = Y + (size_t)srcs[ee+1]*512;
            uint4 vA0 = ysA[tid], vA1 = ysA[tid + 256];
            uint4 vB0 = ysB[tid], vB1 = ysB[tid + 256];
            float cA0 = coefw[ee*TT + t0],     cA1 = coefw[ee*TT + t0 + 32];
            float cB0 = coefw[(ee+1)*TT + t0], cB1 = coefw[(ee+1)*TT + t0 + 32];
            float2 f;
            f = __half22float2(*(const __half2*)&vA0.x); a0[0] += cA0*f.x; a0[1] += cA0*f.y;
            f = __half22float2(*(const __half2*)&vA0.y); a0[2] += cA0*f.x; a0[3] += cA0*f.y;
            f = __half22float2(*(const __half2*)&vA0.z); a0[4] += cA0*f.x; a0[5] += cA0*f.y;
            f = __half22float2(*(const __half2*)&vA0.w); a0[6] += cA0*f.x; a0[7] += cA0*f.y;
            f = __half22float2(*(const __half2*)&vA1.x); a1[0] += cA1*f.x; a1[1] += cA1*f.y;
            f = __half22float2(*(const __half2*)&vA1.y); a1[2] += cA1*f.x; a1[3] += cA1*f.y;
            f = __half22float2(*(const __half2*)&vA1.z); a1[4] += cA1*f.x; a1[5] += cA1*f.y;
            f = __half22float2(*(const __half2*)&vA1.w); a1[6] += cA1*f.x; a1[7] += cA1*f.y;
            f = __half22float2(*(const __half2*)&vB0.x); a0[0] += cB0*f.x; a0[1] += cB0*f.y;
            f = __half22float2(*(const __half2*)&vB0.y); a0[2] += cB0*f.x; a0[3] += cB0*f.y;
            f = __half22float2(*(const __half2*)&vB0.z); a0[4] += cB0*f.x; a0[5] += cB0*f.y;
            f = __half22float2(*(const __half2*)&vB0.w); a0[6] += cB0*f.x; a0[7] += cB0*f.y;
            f = __half22float2(*(const __half2*)&vB1.x); a1[0] += cB1*f.x; a1[1] += cB1*f.y;
            f = __half22float2(*(const __half2*)&vB1.y); a1[2] += cB1*f.x; a1[3] += cB1*f.y;
            f = __half22float2(*(const __half2*)&vB1.z); a1[4] += cB1*f.x; a1[5] += cB1*f.y;
            f = __half22float2(*(const __half2*)&vB1.w); a1[6] += cB1*f.x; a1[7] += cB1*f.y;
        }
        if (ee < cn) {
            const uint4* ys = Y + (size_t)srcs[ee]*512;
            uint4 v0 = ys[tid], v1 = ys[tid + 256];
            float c0f = coefw[ee*TT + t0], c1f = coefw[ee*TT + t0 + 32];
            float2 f;
            f = __half22float2(*(const __half2*)&v0.x); a0[0] += c0f*f.x; a0[1] += c0f*f.y;
            f = __half22float2(*(const __half2*)&v0.y); a0[2] += c0f*f.x; a0[3] += c0f*f.y;
            f = __half22float2(*(const __half2*)&v0.z); a0[4] += c0f*f.x; a0[5] += c0f*f.y;
            f = __half22float2(*(const __half2*)&v0.w); a0[6] += c0f*f.x; a0[7] += c0f*f.y;
            f = __half22float2(*(const __half2*)&v1.x); a1[0] += c1f*f.x; a1[1] += c1f*f.y;
            f = __half22float2(*(const __half2*)&v1.y); a1[2] += c1f*f.x; a1[3] += c1f*f.y;
            f = __half22float2(*(const __half2*)&v1.z); a1[4] += c1f*f.x; a1[5] += c1f*f.y;
            f = __half22float2(*(const __half2*)&v1.w); a1[6] += c1f*f.x; a1[7] += c1f*f.y;
        }
        __syncthreads();
    }

    zpart[q*TT + t] = zloc;
    __syncthreads();
    if (tid < TT) {
        float z = zpart[t] + zpart[TT+t] + zpart[2*TT+t] + zpart[3*TT+t];
        zinv[t] = 1.f/(z + 1e-16f);
    }
    __syncthreads();

    if (deg > 0) {
        float4* O4 = (float4*)(out + (size_t)d*TT*HH);
        float i0v = zinv[t0], i1v = zinv[t0+32];
        float4 o;
        o = O4[tid*2];
        o.x += a0[0]*i0v; o.y += a0[1]*i0v; o.z += a0[2]*i0v; o.w += a0[3]*i0v;
        O4[tid*2] = o;
        o = O4[tid*2+1];
        o.x += a0[4]*i0v; o.y += a0[5]*i0v; o.z += a0[6]*i0v; o.w += a0[7]*i0v;
        O4[tid*2+1] = o;
        o = O4[(tid+256)*2];
        o.x += a1[0]*i1v; o.y += a1[1]*i1v; o.z += a1[2]*i1v; o.w += a1[3]*i1v;
        O4[(tid+256)*2] = o;
        o = O4[(tid+256)*2+1];
        o.x += a1[4]*i1v; o.y += a1[5]*i1v; o.z += a1[6]*i1v; o.w += a1[7]*i1v;
        O4[(tid+256)*2+1] = o;
    }
}

// ---------------- launch ----------------
extern "C" void kernel_launch(void* const* d_in, const int* in_sizes, int n_in,
                              void* d_out, int out_size) {
    const float* x   = (const float*)d_in[0];
    const int*   fei = (const int*)  d_in[1];
    const float* fea = (const float*)d_in[2];
    const float* npw = (const float*)d_in[3];
    const float* ml  = (const float*)d_in[4];
    const float* tw  = (const float*)d_in[5];
    const float* tb  = (const float*)d_in[6];
    const float* lmw = (const float*)d_in[7];
    const float* lmb = (const float*)d_in[8];
    const float* lsw = (const float*)d_in[9];
    const float* lsb = (const float*)d_in[10];
    const float* asw = (const float*)d_in[11];
    const float* asb = (const float*)d_in[12];
    const float* adw = (const float*)d_in[13];
    const float* adb = (const float*)d_in[14];
    float* out = (float*)d_out;

    cudaFuncSetAttribute(k_node, cudaFuncAttributeMaxDynamicSharedMemorySize, SM_BYTES);
    cudaFuncSetAttribute(k_topk, cudaFuncAttributeMaxDynamicSharedMemorySize, TK_SM_BYTES);

    k_embed  <<<NN, 64>>>(x, npw);
    k_topk   <<<NN/RPB, 256, TK_SM_BYTES>>>(ml);
    k_zero_deg<<<(NN+255)/256, 256>>>();
    k_node   <<<NN, 256, SM_BYTES>>>(x, tw, tb, lmw, lmb, lsw, lsb, asw, asb, adw, adb, out);
    k_deg    <<<(EE+255)/256, 256>>>(fei);
    k_scan   <<<1, 1024>>>();
    k_scatter<<<(EE+255)/256, 256>>>(fei, fea, ml);
    k_aggr   <<<NN, 256>>>(out);
}

// round 7
// speedup vs baseline: 1.1561x; 1.1561x over previous
#include <cuda_runtime.h>
#include <cuda_fp16.h>
#include <math.h>

#define NN 2000
#define TT 64
#define HH 64
#define KK 10
#define PD 32
#define EF 32000
#define EK (NN*KK)
#define EE (EF+EK)
#define RPB 8     // topk rows per block

// ---------------- scratch (static __device__, no allocation) ----------------
__device__ float g_e[NN*PD];          // normalized embeddings
__device__ int   g_knn_dst[EK];
__device__ float g_knn_w[EK];         // vals * alpha
__device__ int   g_deg[NN];
__device__ int   g_rowstart[NN+1];
__device__ int   g_cursor[NN];
__device__ int   g_csr_src[EE];
__device__ float g_csr_w[EE];
__device__ __half g_yh[(size_t)NN*TT*HH];  // combined conv output, fp16 (16MB, L2-resident)
__device__ float g_p[NN*TT];          // xt . att_src + b
__device__ float g_q[NN*TT];          // xt . att_dst + b
// precombined weights
__device__ float g_wc[HH*192];        // Wc[c][i*3+k] = sum_o lmw[c,o] tw[o,i,k]
__device__ float g_bc[HH];            // sum_o lmw[c,o] tb[o] + lmb[c]
__device__ float g_va[192];           // sum_o asw[o] tw[o,i,k]
__device__ float g_vd[192];           // sum_o adw[o] tw[o,i,k]
__device__ float g_pq[2];             // pb, qb

// ---------------- packed f32x2 helpers ----------------
__device__ __forceinline__ void ffma2(unsigned long long& d, unsigned long long a, unsigned long long b) {
    asm("fma.rn.f32x2 %0, %1, %2, %0;" : "+l"(d) : "l"(a), "l"(b));
}
__device__ __forceinline__ float upk_sum(unsigned long long v) {
    float lo, hi;
    asm("mov.b64 {%0,%1}, %2;" : "=f"(lo), "=f"(hi) : "l"(v));
    return lo + hi;
}

// ---------------- K0: precombine weights ----------------
__global__ void k_prep(const float* __restrict__ tw, const float* __restrict__ tb,
                       const float* __restrict__ lmw, const float* __restrict__ lmb,
                       const float* __restrict__ asw, const float* __restrict__ asb,
                       const float* __restrict__ adw, const float* __restrict__ adb) {
    int b = blockIdx.x; int j = threadIdx.x;   // 192 threads
    if (b < HH) {
        __shared__ float lr[HH];
        if (j < HH) lr[j] = lmw[b*HH + j];
        __syncthreads();
        float acc = 0.f;
        for (int o = 0; o < HH; o++) acc += lr[o]*tw[o*192 + j];
        g_wc[b*192 + j] = acc;
        if (j == 0) {
            float bacc = 0.f;
            for (int o = 0; o < HH; o++) bacc += lr[o]*tb[o];
            g_bc[b] = bacc + lmb[b];
        }
    } else {
        float a = 0.f, d2 = 0.f;
        for (int o = 0; o < HH; o++) { float t = tw[o*192 + j]; a += asw[o]*t; d2 += adw[o]*t; }
        g_va[j] = a; g_vd[j] = d2;
        if (j == 0) {
            float pa = 0.f, qa = 0.f;
            for (int o = 0; o < HH; o++) { pa += asw[o]*tb[o]; qa += adw[o]*tb[o]; }
            g_pq[0] = pa + asb[0]; g_pq[1] = qa + adb[0];
        }
    }
}

// ---------------- K1: x_agg -> e (normalized), p/q, zero deg ----------------
__global__ void k_embed(const float* __restrict__ x, const float* __restrict__ npw) {
    int n = blockIdx.x; int h = threadIdx.x;      // 64 threads
    __shared__ float xsp[66*65];                  // padded, halo rows 0 and 65 zero
    __shared__ float xa[HH];
    __shared__ float ev[PD];
    __shared__ float sva[192], svd[192];
    if (h == 0) g_deg[n] = 0;
    const float* xn = x + (size_t)n*TT*HH;
    for (int idx = h; idx < TT*HH; idx += 64) {
        int r = idx >> 6, c = idx & 63;
        xsp[(r+1)*65 + c] = xn[idx];
    }
    if (h < 64) {
        xsp[h] = 0.f; xsp[65*65 + h] = 0.f;
        if (h == 0) { xsp[64] = 0.f; xsp[65*65 + 64] = 0.f; }
    }
    for (int idx = h; idx < 192; idx += 64) { sva[idx] = g_va[idx]; svd[idx] = g_vd[idx]; }
    __syncthreads();

    // mean over t (column h)
    float s = 0.f;
    #pragma unroll
    for (int t = 0; t < TT; t++) s += xsp[(t+1)*65 + h];
    xa[h] = s * (1.0f/TT);
    __syncthreads();
    if (h < PD) {
        float acc = 0.f;
        #pragma unroll
        for (int c = 0; c < HH; c++) acc += xa[c] * npw[h*HH + c];
        ev[h] = acc;
    }
    __syncthreads();
    if (h < PD) {
        float v = ev[h];
        float ss = v*v;
        #pragma unroll
        for (int o = 16; o > 0; o >>= 1) ss += __shfl_xor_sync(0xffffffffu, ss, o);
        float nrm = fmaxf(sqrtf(ss), 1e-12f);
        g_e[n*PD + h] = v / nrm;
    }

    // p/q: 1-channel convs of x with va/vd, thread h handles t=h
    float pp = 0.f, qq = 0.f;
    #pragma unroll
    for (int k = 0; k < 3; k++) {
        #pragma unroll 8
        for (int i = 0; i < HH; i++) {
            float v = xsp[(h+k)*65 + i];
            pp += v * sva[i*3 + k];
            qq += v * svd[i*3 + k];
        }
    }
    g_p[n*TT + h] = pp + g_pq[0];
    g_q[n*TT + h] = qq + g_pq[1];
}

// ---------------- K2: 8 rows per block, warp-per-row top-(K+1) + degrees ----------------
#define TK_SM_FLOATS (RPB*NN + RPB*PD)
#define TK_SM_BYTES  (TK_SM_FLOATS*4)
__global__ void __launch_bounds__(256) k_topk(const float* __restrict__ mix_logit,
                                              const int* __restrict__ fei) {
    extern __shared__ float smt[];
    float* sim = smt;
    float* ei  = smt + RPB*NN;
    int i0 = blockIdx.x * RPB;
    int tid = threadIdx.x;

    for (int idx = tid; idx < RPB*PD; idx += 256) ei[idx] = g_e[i0*PD + idx];
    __syncthreads();

    for (int j = tid; j < NN; j += 256) {
        const float4* ej = (const float4*)(g_e + j*PD);
        float4 ev[8];
        #pragma unroll
        for (int c = 0; c < 8; c++) ev[c] = ej[c];
        #pragma unroll
        for (int r = 0; r < RPB; r++) {
            const float4* er = (const float4*)(ei + r*PD);
            float dsum = 0.f;
            #pragma unroll
            for (int c = 0; c < 8; c++) {
                float4 e4 = er[c];
                dsum += ev[c].x*e4.x + ev[c].y*e4.y + ev[c].z*e4.z + ev[c].w*e4.w;
            }
            sim[r*NN + j] = dsum;
        }
    }
    __syncthreads();

    float alpha = 1.f/(1.f + expf(-mix_logit[0]));
    int w = tid >> 5, lane = tid & 31;
    int i = i0 + w;
    float* simr = sim + w*NN;
    int mydst = -1;
    for (int k = 0; k <= KK; k++) {
        float bv = -INFINITY; int bi = NN;
        for (int j = lane; j < NN; j += 32) {
            float v = simr[j];
            if (v > bv || (v == bv && j < bi)) { bv = v; bi = j; }
        }
        #pragma unroll
        for (int off = 16; off > 0; off >>= 1) {
            float ov = __shfl_down_sync(0xffffffffu, bv, off);
            int   oi = __shfl_down_sync(0xffffffffu, bi, off);
            if (ov > bv || (ov == bv && oi < bi)) { bv = ov; bi = oi; }
        }
        bi = __shfl_sync(0xffffffffu, bi, 0);
        bv = __shfl_sync(0xffffffffu, bv, 0);
        if (k > 0 && lane == k-1) mydst = bi;     // keep own knn dst in register
        if (lane == 0) {
            if (k > 0) { g_knn_dst[i*KK + (k-1)] = bi; g_knn_w[i*KK + (k-1)] = bv*alpha; }
            simr[bi] = -INFINITY;
        }
        __syncwarp();
    }
    // degree atomics: knn edges of this row + a slice of fixed edges
    if (lane < KK) atomicAdd(&g_deg[mydst], 1);
    int e = blockIdx.x*256 + tid;
    if (e < EF) atomicAdd(&g_deg[fei[EF + e]], 1);
}

// ---------------- K3 (scan) ----------------
__global__ void k_scan() {                         // 1 block, 1024 threads
    __shared__ int a[2048], b[2048];
    int tid = threadIdx.x;
    for (int i = tid; i < 2048; i += 1024) a[i] = (i < NN) ? g_deg[i] : 0;
    __syncthreads();
    int* in = a; int* out = b;
    for (int off = 1; off < 2048; off <<= 1) {
        for (int i = tid; i < 2048; i += 1024)
            out[i] = in[i] + (i >= off ? in[i-off] : 0);
        __syncthreads();
        int* t = in; in = out; out = t;
    }
    for (int i = tid; i <= NN; i += 1024) {
        int rs = (i == 0) ? 0 : in[i-1];
        g_rowstart[i] = rs;
        if (i < NN) g_cursor[i] = rs;
    }
}

__global__ void k_scatter(const int* __restrict__ fei, const float* __restrict__ fea,
                          const float* __restrict__ mix_logit) {
    int e = blockIdx.x*blockDim.x + threadIdx.x;
    if (e >= EE) return;
    float alpha = 1.f/(1.f + expf(-mix_logit[0]));
    int s, d; float w;
    if (e < EF) { s = fei[e]; d = fei[EF + e]; w = fea[e]*(1.f - alpha); }
    else { int ke = e - EF; s = ke / KK; d = g_knn_dst[ke]; w = g_knn_w[ke]; }
    int pos = atomicAdd(&g_cursor[d], 1);
    g_csr_src[pos] = s; g_csr_w[pos] = w;
}

// ---------------- K4: fused self GEMM + combined conv -> y (fp16) ----------------
// R5 structure, phases 1-4 only; conv weights = g_wc; no xts.
// smem (floats): xs 4224 | wp 6240  -> 41856 B
#define XS_OFF   0
#define WP_OFF   ((TT+2)*HH)
#define SM_FLOATS (WP_OFF + 6240)
#define SM_BYTES  (SM_FLOATS*4)

__global__ void __launch_bounds__(256, 3) k_node(
    const float* __restrict__ x,
    const float* __restrict__ lsw, const float* __restrict__ lsb,
    float* __restrict__ out)
{
    extern __shared__ float sm[];
    float* xs  = sm + XS_OFF;
    float* wpf = sm + WP_OFF;
    float2* wp2 = (float2*)wpf;
    unsigned long long* wpu = (unsigned long long*)wpf;
    const ulonglong2* xsu  = (const ulonglong2*)xs;

    int n = blockIdx.x;
    int tid = threadIdx.x;
    int o = tid & 31;            // channels o and o+32
    int tc = tid >> 5;           // 8 row-slices
    int base = tc * 8;

    // phase 1: load x (halo) + stage lsw packed
    const float* xn = x + (size_t)n*TT*HH;
    for (int idx = tid; idx < TT*HH; idx += 256) xs[idx + HH] = xn[idx];
    for (int idx = tid; idx < HH; idx += 256) { xs[idx] = 0.f; xs[(TT+1)*HH + idx] = 0.f; }
    {
        const float2* w2 = (const float2*)lsw;
        #pragma unroll
        for (int it = 0; it < 8; it++) {
            int idx = it*256 + tid;
            int oc = idx >> 5, ip = idx & 31;
            wp2[ip*65 + oc] = w2[idx];
        }
    }
    __syncthreads();

    unsigned long long aA[8], aB[8];

    // phase 2: self term -> out : x @ Wself^T + b
    {
        #pragma unroll
        for (int tt = 0; tt < 8; tt++) { aA[tt] = 0ULL; aB[tt] = 0ULL; }
        #pragma unroll 4
        for (int ip2 = 0; ip2 < 16; ip2++) {
            unsigned long long wA0 = wpu[(2*ip2)*65 + o];
            unsigned long long wB0 = wpu[(2*ip2)*65 + o + 32];
            unsigned long long wA1 = wpu[(2*ip2+1)*65 + o];
            unsigned long long wB1 = wpu[(2*ip2+1)*65 + o + 32];
            #pragma unroll
            for (int tt = 0; tt < 8; tt++) {
                ulonglong2 xv = xsu[(base+tt+1)*16 + ip2];
                ffma2(aA[tt], xv.x, wA0); ffma2(aA[tt], xv.y, wA1);
                ffma2(aB[tt], xv.x, wB0); ffma2(aB[tt], xv.y, wB1);
            }
        }
        float* op = out + (size_t)n*TT*HH;
        float sbA = lsb[o], sbB = lsb[o+32];
        #pragma unroll
        for (int tt = 0; tt < 8; tt++) {
            op[(base+tt)*HH + o]      = upk_sum(aA[tt]) + sbA;
            op[(base+tt)*HH + o + 32] = upk_sum(aB[tt]) + sbB;
        }
    }

    // phases 3-4: combined conv with g_wc -> y fp16 (two i-halves, wp restaged)
    #pragma unroll
    for (int tt = 0; tt < 8; tt++) { aA[tt] = 0ULL; aB[tt] = 0ULL; }
    for (int h = 0; h < 2; h++) {
        __syncthreads();
        #pragma unroll
        for (int it = 0; it < 24; it++) {
            int idx = it*256 + tid;              // [0, 6144)
            int oc = idx / 96, j = idx - oc*96;  // j = il*3 + k
            int il = j / 3, k = j - il*3;
            int ip = il >> 1, comp = il & 1;
            wpf[((k*16 + ip)*65 + oc)*2 + comp] = g_wc[oc*192 + h*96 + j];
        }
        __syncthreads();
        #pragma unroll 2
        for (int ip2 = 0; ip2 < 8; ip2++) {
            int lp0 = 2*ip2, lp1 = 2*ip2+1;
            unsigned long long w0A0 = wpu[(0*16+lp0)*65 + o],      w0A1 = wpu[(0*16+lp1)*65 + o];
            unsigned long long w0B0 = wpu[(0*16+lp0)*65 + o + 32], w0B1 = wpu[(0*16+lp1)*65 + o + 32];
            unsigned long long w1A0 = wpu[(1*16+lp0)*65 + o],      w1A1 = wpu[(1*16+lp1)*65 + o];
            unsigned long long w1B0 = wpu[(1*16+lp0)*65 + o + 32], w1B1 = wpu[(1*16+lp1)*65 + o + 32];
            unsigned long long w2A0 = wpu[(2*16+lp0)*65 + o],      w2A1 = wpu[(2*16+lp1)*65 + o];
            unsigned long long w2B0 = wpu[(2*16+lp0)*65 + o + 32], w2B1 = wpu[(2*16+lp1)*65 + o + 32];
            int ig = h*8 + ip2;
            ulonglong2 r0 = xsu[(base+0)*16 + ig];
            ulonglong2 r1 = xsu[(base+1)*16 + ig];
            #pragma unroll
            for (int tt = 0; tt < 8; tt++) {
                ulonglong2 r2 = xsu[(base+tt+2)*16 + ig];
                ffma2(aA[tt], r0.x, w0A0); ffma2(aA[tt], r0.y, w0A1);
                ffma2(aA[tt], r1.x, w1A0); ffma2(aA[tt], r1.y, w1A1);
                ffma2(aA[tt], r2.x, w2A0); ffma2(aA[tt], r2.y, w2A1);
                ffma2(aB[tt], r0.x, w0B0); ffma2(aB[tt], r0.y, w0B1);
                ffma2(aB[tt], r1.x, w1B0); ffma2(aB[tt], r1.y, w1B1);
                ffma2(aB[tt], r2.x, w2B0); ffma2(aB[tt], r2.y, w2B1);
                r0 = r1; r1 = r2;
            }
        }
    }
    {
        __half* yp = g_yh + (size_t)n*TT*HH;
        float bcA = g_bc[o], bcB = g_bc[o+32];
        #pragma unroll
        for (int tt = 0; tt < 8; tt++) {
            yp[(base+tt)*HH + o]      = __float2half_rn(upk_sum(aA[tt]) + bcA);
            yp[(base+tt)*HH + o + 32] = __float2half_rn(upk_sum(aB[tt]) + bcB);
        }
    }
}

// ---------------- K5: per-dst softmax + aggregation (fp16 y gather) ----------------
#define CH 16
__global__ void __launch_bounds__(256) k_aggr(float* __restrict__ out) {
    __shared__ float coefw[CH*TT];
    __shared__ int   srcs[CH];
    __shared__ float ws[CH];
    __shared__ float qv[TT];
    __shared__ float ms[TT];
    __shared__ float mpart[4*TT];
    __shared__ float zpart[4*TT];
    __shared__ float zinv[TT];

    int d = blockIdx.x, tid = threadIdx.x;
    int t = tid & 63, q = tid >> 6;
    int r0 = g_rowstart[d], r1 = g_rowstart[d+1];
    int deg = r1 - r0;
    if (tid < TT) qv[tid] = g_q[d*TT + tid];
    __syncthreads();
    float qvt = qv[t];

    float m = -INFINITY;
    for (int e = r0 + q; e < r1; e += 4) {
        int s = g_csr_src[e];
        float a = g_p[s*TT + t] + qvt;
        a = a > 0.f ? a : 0.2f*a;
        m = fmaxf(m, a);
    }
    mpart[q*TT + t] = m;
    __syncthreads();
    if (tid < TT) {
        ms[t] = fmaxf(fmaxf(mpart[t], mpart[TT+t]), fmaxf(mpart[2*TT+t], mpart[3*TT+t]));
    }
    __syncthreads();
    float mt = ms[t];

    float a0[8], a1[8];
    #pragma unroll
    for (int j = 0; j < 8; j++) { a0[j] = 0.f; a1[j] = 0.f; }
    float zloc = 0.f;
    int t0 = tid >> 3;
    const uint4* Y = (const uint4*)g_yh;

    for (int c0 = r0; c0 < r1; c0 += CH) {
        int cn = min(CH, r1 - c0);
        if (tid < cn) { srcs[tid] = g_csr_src[c0+tid]; ws[tid] = g_csr_w[c0+tid]; }
        __syncthreads();
        #pragma unroll
        for (int k = 0; k < 4; k++) {
            int ee = q + 4*k;
            if (ee < cn) {
                int s = srcs[ee];
                float a = g_p[s*TT + t] + qvt;
                a = a > 0.f ? a : 0.2f*a;
                float cc = __expf(a - mt);
                zloc += cc;
                coefw[ee*TT + t] = cc * ws[ee];
            }
        }
        __syncthreads();
        int ee = 0;
        for (; ee + 1 < cn; ee += 2) {
            const uint4* ysA = Y + (size_t)srcs[ee]*512;
            const uint4* ysB = Y + (size_t)srcs[ee+1]*512;
            uint4 vA0 = ysA[tid], vA1 = ysA[tid + 256];
            uint4 vB0 = ysB[tid], vB1 = ysB[tid + 256];
            float cA0 = coefw[ee*TT + t0],     cA1 = coefw[ee*TT + t0 + 32];
            float cB0 = coefw[(ee+1)*TT + t0], cB1 = coefw[(ee+1)*TT + t0 + 32];
            float2 f;
            f = __half22float2(*(const __half2*)&vA0.x); a0[0] += cA0*f.x; a0[1] += cA0*f.y;
            f = __half22float2(*(const __half2*)&vA0.y); a0[2] += cA0*f.x; a0[3] += cA0*f.y;
            f = __half22float2(*(const __half2*)&vA0.z); a0[4] += cA0*f.x; a0[5] += cA0*f.y;
            f = __half22float2(*(const __half2*)&vA0.w); a0[6] += cA0*f.x; a0[7] += cA0*f.y;
            f = __half22float2(*(const __half2*)&vA1.x); a1[0] += cA1*f.x; a1[1] += cA1*f.y;
            f = __half22float2(*(const __half2*)&vA1.y); a1[2] += cA1*f.x; a1[3] += cA1*f.y;
            f = __half22float2(*(const __half2*)&vA1.z); a1[4] += cA1*f.x; a1[5] += cA1*f.y;
            f = __half22float2(*(const __half2*)&vA1.w); a1[6] += cA1*f.x; a1[7] += cA1*f.y;
            f = __half22float2(*(const __half2*)&vB0.x); a0[0] += cB0*f.x; a0[1] += cB0*f.y;
            f = __half22float2(*(const __half2*)&vB0.y); a0[2] += cB0*f.x; a0[3] += cB0*f.y;
            f = __half22float2(*(const __half2*)&vB0.z); a0[4] += cB0*f.x; a0[5] += cB0*f.y;
            f = __half22float2(*(const __half2*)&vB0.w); a0[6] += cB0*f.x; a0[7] += cB0*f.y;
            f = __half22float2(*(const __half2*)&vB1.x); a1[0] += cB1*f.x; a1[1] += cB1*f.y;
            f = __half22float2(*(const __half2*)&vB1.y); a1[2] += cB1*f.x; a1[3] += cB1*f.y;
            f = __half22float2(*(const __half2*)&vB1.z); a1[4] += cB1*f.x; a1[5] += cB1*f.y;
            f = __half22float2(*(const __half2*)&vB1.w); a1[6] += cB1*f.x; a1[7] += cB1*f.y;
        }
        if (ee < cn) {
            const uint4* ys = Y + (size_t)srcs[ee]*512;
            uint4 v0 = ys[tid], v1 = ys[tid + 256];
            float c0f = coefw[ee*TT + t0], c1f = coefw[ee*TT + t0 + 32];
            float2 f;
            f = __half22float2(*(const __half2*)&v0.x); a0[0] += c0f*f.x; a0[1] += c0f*f.y;
            f = __half22float2(*(const __half2*)&v0.y); a0[2] += c0f*f.x; a0[3] += c0f*f.y;
            f = __half22float2(*(const __half2*)&v0.z); a0[4] += c0f*f.x; a0[5] += c0f*f.y;
            f = __half22float2(*(const __half2*)&v0.w); a0[6] += c0f*f.x; a0[7] += c0f*f.y;
            f = __half22float2(*(const __half2*)&v1.x); a1[0] += c1f*f.x; a1[1] += c1f*f.y;
            f = __half22float2(*(const __half2*)&v1.y); a1[2] += c1f*f.x; a1[3] += c1f*f.y;
            f = __half22float2(*(const __half2*)&v1.z); a1[4] += c1f*f.x; a1[5] += c1f*f.y;
            f = __half22float2(*(const __half2*)&v1.w); a1[6] += c1f*f.x; a1[7] += c1f*f.y;
        }
        __syncthreads();
    }

    zpart[q*TT + t] = zloc;
    __syncthreads();
    if (tid < TT) {
        float z = zpart[t] + zpart[TT+t] + zpart[2*TT+t] + zpart[3*TT+t];
        zinv[t] = 1.f/(z + 1e-16f);
    }
    __syncthreads();

    if (deg > 0) {
        float4* O4 = (float4*)(out + (size_t)d*TT*HH);
        float i0v = zinv[t0], i1v = zinv[t0+32];
        float4 o;
        o = O4[tid*2];
        o.x += a0[0]*i0v; o.y += a0[1]*i0v; o.z += a0[2]*i0v; o.w += a0[3]*i0v;
        O4[tid*2] = o;
        o = O4[tid*2+1];
        o.x += a0[4]*i0v; o.y += a0[5]*i0v; o.z += a0[6]*i0v; o.w += a0[7]*i0v;
        O4[tid*2+1] = o;
        o = O4[(tid+256)*2];
        o.x += a1[0]*i1v; o.y += a1[1]*i1v; o.z += a1[2]*i1v; o.w += a1[3]*i1v;
        O4[(tid+256)*2] = o;
        o = O4[(tid+256)*2+1];
        o.x += a1[4]*i1v; o.y += a1[5]*i1v; o.z += a1[6]*i1v; o.w += a1[7]*i1v;
        O4[(tid+256)*2+1] = o;
    }
}

// ---------------- launch ----------------
extern "C" void kernel_launch(void* const* d_in, const int* in_sizes, int n_in,
                              void* d_out, int out_size) {
    const float* x   = (const float*)d_in[0];
    const int*   fei = (const int*)  d_in[1];
    const float* fea = (const float*)d_in[2];
    const float* npw = (const float*)d_in[3];
    const float* ml  = (const float*)d_in[4];
    const float* tw  = (const float*)d_in[5];
    const float* tb  = (const float*)d_in[6];
    const float* lmw = (const float*)d_in[7];
    const float* lmb = (const float*)d_in[8];
    const float* lsw = (const float*)d_in[9];
    const float* lsb = (const float*)d_in[10];
    const float* asw = (const float*)d_in[11];
    const float* asb = (const float*)d_in[12];
    const float* adw = (const float*)d_in[13];
    const float* adb = (const float*)d_in[14];
    float* out = (float*)d_out;

    cudaFuncSetAttribute(k_node, cudaFuncAttributeMaxDynamicSharedMemorySize, SM_BYTES);
    cudaFuncSetAttribute(k_topk, cudaFuncAttributeMaxDynamicSharedMemorySize, TK_SM_BYTES);

    k_prep   <<<HH+1, 192>>>(tw, tb, lmw, lmb, asw, asb, adw, adb);
    k_embed  <<<NN, 64>>>(x, npw);
    k_topk   <<<NN/RPB, 256, TK_SM_BYTES>>>(ml, fei);
    k_node   <<<NN, 256, SM_BYTES>>>(x, lsw, lsb, out);   // 4th launch: ncu capture slot
    k_scan   <<<1, 1024>>>();
    k_scatter<<<(EE+255)/256, 256>>>(fei, fea, ml);
    k_aggr   <<<NN, 256>>>(out);
}

// round 13
// speedup vs baseline: 1.6643x; 1.4395x over previous
#include <cuda_runtime.h>
#include <cuda_fp16.h>
#include <mma.h>
#include <math.h>

using namespace nvcuda;

#define NN 2000
#define TT 64
#define HH 64
#define KK 10
#define PD 32
#define EF 32000
#define EK (NN*KK)
#define EE (EF+EK)
#define RPB 8

typedef unsigned int u32;

// ---------------- scratch (static __device__, no allocation) ----------------
__device__ float g_e[NN*PD];
__device__ int   g_knn_dst[EK];
__device__ float g_knn_w[EK];
__device__ int   g_deg[NN];
__device__ int   g_rowstart[NN+1];
__device__ int   g_cursor[NN];
__device__ int   g_csr_src[EE];
__device__ float g_csr_w[EE];
__device__ __half g_yh[(size_t)NN*TT*HH];
__device__ float g_p[NN*TT];
__device__ float g_q[NN*TT];
__device__ __half g_wkh[3*HH*HH];
__device__ __half g_lswh[HH*HH];
__device__ float g_bc[HH];
__device__ float g_va[192];
__device__ float g_vd[192];
__device__ float g_pq[2];

// ---------------- K0: precombine weights (fp16 outputs) ----------------
__global__ void k_prep(const float* __restrict__ tw, const float* __restrict__ tb,
                       const float* __restrict__ lmw, const float* __restrict__ lmb,
                       const float* __restrict__ asw, const float* __restrict__ asb,
                       const float* __restrict__ adw, const float* __restrict__ adb,
                       const float* __restrict__ lsw) {
    int b = blockIdx.x;
    int j = threadIdx.x;
    if (b < HH) {
        __shared__ float lr[HH];
        if (j < HH) lr[j] = lmw[b*HH + j];
        __syncthreads();
        float acc = 0.f;
        for (int o = 0; o < HH; o++) acc += lr[o]*tw[o*192 + j];
        int i = j/3;
        int k = j - 3*i;
        g_wkh[k*HH*HH + b*HH + i] = __float2half_rn(acc);
        if (j == 0) {
            float bacc = 0.f;
            for (int o = 0; o < HH; o++) bacc += lr[o]*tb[o];
            g_bc[b] = bacc + lmb[b];
        }
    } else {
        float a = 0.f;
        float d2 = 0.f;
        for (int o = 0; o < HH; o++) {
            float t = tw[o*192 + j];
            a += asw[o]*t;
            d2 += adw[o]*t;
        }
        g_va[j] = a;
        g_vd[j] = d2;
        if (j == 0) {
            float pa = 0.f;
            float qa = 0.f;
            for (int o = 0; o < HH; o++) {
                pa += asw[o]*tb[o];
                qa += adw[o]*tb[o];
            }
            g_pq[0] = pa + asb[0];
            g_pq[1] = qa + adb[0];
        }
        for (int idx = j; idx < HH*HH; idx += 192) g_lswh[idx] = __float2half_rn(lsw[idx]);
    }
}

// ---------------- K1: x_agg -> e (normalized), p/q, zero deg ----------------
__global__ void k_embed(const float* __restrict__ x, const float* __restrict__ npw) {
    int n = blockIdx.x;
    int h = threadIdx.x;
    __shared__ float xsp[66*65];
    __shared__ float xa[HH];
    __shared__ float ev[PD];
    __shared__ float sva[192];
    __shared__ float svd[192];
    if (h == 0) g_deg[n] = 0;
    const float* xn = x + (size_t)n*TT*HH;
    for (int idx = h; idx < TT*HH; idx += 64) {
        int r = idx >> 6;
        int c = idx & 63;
        xsp[(r+1)*65 + c] = xn[idx];
    }
    xsp[h] = 0.f;
    xsp[65*65 + h] = 0.f;
    if (h == 0) {
        xsp[64] = 0.f;
        xsp[65*65 + 64] = 0.f;
    }
    for (int idx = h; idx < 192; idx += 64) {
        sva[idx] = g_va[idx];
        svd[idx] = g_vd[idx];
    }
    __syncthreads();

    float s = 0.f;
    #pragma unroll
    for (int t = 0; t < TT; t++) {
        s += xsp[(t+1)*65 + h];
    }
    xa[h] = s * (1.0f/TT);
    __syncthreads();
    if (h < PD) {
        float acc = 0.f;
        #pragma unroll
        for (int c = 0; c < HH; c++) {
            acc += xa[c] * npw[h*HH + c];
        }
        ev[h] = acc;
    }
    __syncthreads();
    if (h < PD) {
        float v = ev[h];
        float ss = v*v;
        #pragma unroll
        for (int o = 16; o > 0; o >>= 1) {
            ss += __shfl_xor_sync(0xffffffffu, ss, o);
        }
        float nrm = fmaxf(sqrtf(ss), 1e-12f);
        g_e[n*PD + h] = v / nrm;
    }

    float pp = 0.f;
    float qq = 0.f;
    #pragma unroll
    for (int k = 0; k < 3; k++) {
        #pragma unroll 8
        for (int i = 0; i < HH; i++) {
            float v = xsp[(h+k)*65 + i];
            pp += v * sva[i*3 + k];
            qq += v * svd[i*3 + k];
        }
    }
    g_p[n*TT + h] = pp + g_pq[0];
    g_q[n*TT + h] = qq + g_pq[1];
}

// ---------------- K2: topk + degree atomics ----------------
#define TK_SM_FLOATS (RPB*NN + RPB*PD)
#define TK_SM_BYTES  (TK_SM_FLOATS*4)
__global__ void __launch_bounds__(256) k_topk(const float* __restrict__ mix_logit,
                                              const int* __restrict__ fei) {
    extern __shared__ float smt[];
    float* sim = smt;
    float* ei  = smt + RPB*NN;
    int i0 = blockIdx.x * RPB;
    int tid = threadIdx.x;

    for (int idx = tid; idx < RPB*PD; idx += 256) ei[idx] = g_e[i0*PD + idx];
    __syncthreads();

    for (int j = tid; j < NN; j += 256) {
        const float4* ej = (const float4*)(g_e + j*PD);
        float4 ev[8];
        #pragma unroll
        for (int c = 0; c < 8; c++) {
            ev[c] = ej[c];
        }
        #pragma unroll
        for (int r = 0; r < RPB; r++) {
            const float4* er = (const float4*)(ei + r*PD);
            float dsum = 0.f;
            #pragma unroll
            for (int c = 0; c < 8; c++) {
                float4 e4 = er[c];
                dsum += ev[c].x*e4.x + ev[c].y*e4.y + ev[c].z*e4.z + ev[c].w*e4.w;
            }
            sim[r*NN + j] = dsum;
        }
    }
    __syncthreads();

    float alpha = 1.f/(1.f + expf(-mix_logit[0]));
    int w = tid >> 5;
    int lane = tid & 31;
    int i = i0 + w;
    float* simr = sim + w*NN;
    int mydst = -1;
    for (int k = 0; k <= KK; k++) {
        float bv = -INFINITY;
        int bi = NN;
        for (int j = lane; j < NN; j += 32) {
            float v = simr[j];
            if (v > bv || (v == bv && j < bi)) { bv = v; bi = j; }
        }
        #pragma unroll
        for (int off = 16; off > 0; off >>= 1) {
            float ov = __shfl_down_sync(0xffffffffu, bv, off);
            int   oi = __shfl_down_sync(0xffffffffu, bi, off);
            if (ov > bv || (ov == bv && oi < bi)) { bv = ov; bi = oi; }
        }
        bi = __shfl_sync(0xffffffffu, bi, 0);
        bv = __shfl_sync(0xffffffffu, bv, 0);
        if (k > 0 && lane == k-1) mydst = bi;
        if (lane == 0) {
            if (k > 0) {
                g_knn_dst[i*KK + (k-1)] = bi;
                g_knn_w[i*KK + (k-1)] = bv*alpha;
            }
            simr[bi] = -INFINITY;
        }
        __syncwarp();
    }
    if (lane < KK) atomicAdd(&g_deg[mydst], 1);
    int e = blockIdx.x*256 + tid;
    if (e < EF) atomicAdd(&g_deg[fei[EF + e]], 1);
}

// ---------------- K3: scan ----------------
__global__ void k_scan() {
    __shared__ int a[2048];
    __shared__ int b[2048];
    int tid = threadIdx.x;
    for (int i = tid; i < 2048; i += 1024) a[i] = (i < NN) ? g_deg[i] : 0;
    __syncthreads();
    int* in = a;
    int* out = b;
    for (int off = 1; off < 2048; off <<= 1) {
        for (int i = tid; i < 2048; i += 1024) {
            out[i] = in[i] + (i >= off ? in[i-off] : 0);
        }
        __syncthreads();
        int* t = in; in = out; out = t;
    }
    for (int i = tid; i <= NN; i += 1024) {
        int rs = (i == 0) ? 0 : in[i-1];
        g_rowstart[i] = rs;
        if (i < NN) g_cursor[i] = rs;
    }
}

__global__ void k_scatter(const int* __restrict__ fei, const float* __restrict__ fea,
                          const float* __restrict__ mix_logit) {
    int e = blockIdx.x*blockDim.x + threadIdx.x;
    if (e >= EE) return;
    float alpha = 1.f/(1.f + expf(-mix_logit[0]));
    int s, d;
    float w;
    if (e < EF) {
        s = fei[e];
        d = fei[EF + e];
        w = fea[e]*(1.f - alpha);
    } else {
        int ke = e - EF;
        s = ke / KK;
        d = g_knn_dst[ke];
        w = g_knn_w[ke];
    }
    int pos = atomicAdd(&g_cursor[d], 1);
    g_csr_src[pos] = s;
    g_csr_w[pos] = w;
}

// ---------------- K4: wmma self GEMM + conv -> out, y(fp16) ----------------
#define XROW 72
#define WH_OFF (66*XROW)
#define SCR_OFF_F ((WH_OFF + 4*HH*XROW)/2)
#define SM_BYTES ((WH_OFF + 4*HH*XROW)*2 + TT*HH*4)

__global__ void __launch_bounds__(256, 3) k_node(
    const float* __restrict__ x,
    const float* __restrict__ lsb,
    float* __restrict__ out)
{
    extern __shared__ float smf[];
    __half* xh = (__half*)smf;
    __half* wh = xh + WH_OFF;
    float* scr = smf + SCR_OFF_F;

    int n = blockIdx.x;
    int tid = threadIdx.x;
    int w = tid >> 5;

    // stage x -> fp16 smem rows 1..64; halo rows 0 and 65 zeroed
    const float4* xn4 = (const float4*)(x + (size_t)n*TT*HH);
    #pragma unroll
    for (int it = 0; it < 4; it++) {
        int idx = it*256 + tid;
        int r = idx >> 4;
        int c4 = (idx & 15) * 4;
        float4 v = xn4[idx];
        __half2* dst = (__half2*)(xh + (r+1)*XROW + c4);
        dst[0] = __floats2half2_rn(v.x, v.y);
        dst[1] = __floats2half2_rn(v.z, v.w);
    }
    if (tid < 32) {
        __half2* z0 = (__half2*)xh;
        z0[tid] = __floats2half2_rn(0.f, 0.f);
    } else if (tid < 64) {
        __half2* z1 = (__half2*)(xh + 65*XROW);
        z1[tid - 32] = __floats2half2_rn(0.f, 0.f);
    }

    // stage weights: mat 0 = lsw, mats 1..3 = Wk
    #pragma unroll
    for (int it = 0; it < 8; it++) {
        int idx = it*256 + tid;
        int mg = idx >> 9;
        int rr = (idx >> 3) & 63;
        int ch = idx & 7;
        const float4* src = (mg == 0) ? (const float4*)g_lswh : (const float4*)(g_wkh + (mg-1)*HH*HH);
        float4 v = src[rr*8 + ch];
        *(float4*)(wh + mg*HH*XROW + rr*XROW + ch*8) = v;
    }
    __syncthreads();

    wmma::fragment<wmma::matrix_a, 16, 16, 16, __half, wmma::row_major> fa;
    wmma::fragment<wmma::matrix_b, 16, 16, 16, __half, wmma::col_major> fb;
    wmma::fragment<wmma::accumulator, 16, 16, 16, float> fc;

    int tile0 = w * 2;

    // ---- self GEMM: D = x @ lsw^T ----
    for (int tile = tile0; tile < tile0 + 2; tile++) {
        int tr = tile >> 2;
        int tc = tile & 3;
        wmma::fill_fragment(fc, 0.f);
        for (int ks = 0; ks < 4; ks++) {
            wmma::load_matrix_sync(fa, xh + (tr*16 + 1)*XROW + ks*16, XROW);
            wmma::load_matrix_sync(fb, wh + (tc*16)*XROW + ks*16, XROW);
            wmma::mma_sync(fc, fa, fb, fc);
        }
        wmma::store_matrix_sync(scr + tr*16*HH + tc*16, fc, HH, wmma::mem_row_major);
    }
    __syncthreads();

    // copy scr + lsb -> out (coalesced)
    float* op = out + (size_t)n*TT*HH;
    #pragma unroll
    for (int it = 0; it < 4; it++) {
        int idx = it*256 + tid;
        float4 v = ((const float4*)scr)[idx];
        int c = (idx & 15) * 4;
        float4 lb = *(const float4*)(lsb + c);
        v.x += lb.x;
        v.y += lb.y;
        v.z += lb.z;
        v.w += lb.w;
        ((float4*)op)[idx] = v;
    }
    __syncthreads();

    // ---- conv: 3 shifted GEMMs accumulated ----
    for (int tile = tile0; tile < tile0 + 2; tile++) {
        int tr = tile >> 2;
        int tc = tile & 3;
        wmma::fill_fragment(fc, 0.f);
        for (int g = 1; g <= 3; g++) {
            for (int ks = 0; ks < 4; ks++) {
                wmma::load_matrix_sync(fa, xh + (tr*16 + (g-1))*XROW + ks*16, XROW);
                wmma::load_matrix_sync(fb, wh + g*HH*XROW + (tc*16)*XROW + ks*16, XROW);
                wmma::mma_sync(fc, fa, fb, fc);
            }
        }
        wmma::store_matrix_sync(scr + tr*16*HH + tc*16, fc, HH, wmma::mem_row_major);
    }
    __syncthreads();

    // copy scr + bc -> g_yh (fp16, coalesced)
    __half* yp = g_yh + (size_t)n*TT*HH;
    #pragma unroll
    for (int it = 0; it < 4; it++) {
        int idx = it*256 + tid;
        float4 v = ((const float4*)scr)[idx];
        int c = (idx & 15) * 4;
        float4 bb = *(const float4*)(g_bc + c);
        __half2* dst = (__half2*)(yp + idx*4);
        dst[0] = __floats2half2_rn(v.x + bb.x, v.y + bb.y);
        dst[1] = __floats2half2_rn(v.z + bb.z, v.w + bb.w);
    }
}

// ---------------- K5: per-dst softmax + aggregation (fp16 y gather) ----------------
#define CH 16
__global__ void __launch_bounds__(256) k_aggr(float* __restrict__ out) {
    __shared__ float coefw[CH*TT];
    __shared__ int   srcs[CH];
    __shared__ float ws[CH];
    __shared__ float qv[TT];
    __shared__ float ms[TT];
    __shared__ float mpart[4*TT];
    __shared__ float zpart[4*TT];
    __shared__ float zinv[TT];

    int d = blockIdx.x;
    int tid = threadIdx.x;
    int t = tid & 63;
    int q = tid >> 6;
    int r0 = g_rowstart[d];
    int r1 = g_rowstart[d+1];
    int deg = r1 - r0;
    if (tid < TT) qv[tid] = g_q[d*TT + tid];
    __syncthreads();
    float qvt = qv[t];

    float m = -INFINITY;
    for (int e = r0 + q; e < r1; e += 4) {
        int s = g_csr_src[e];
        float a = g_p[s*TT + t] + qvt;
        a = a > 0.f ? a : 0.2f*a;
        m = fmaxf(m, a);
    }
    mpart[q*TT + t] = m;
    __syncthreads();
    if (tid < TT) {
        ms[t] = fmaxf(fmaxf(mpart[t], mpart[TT+t]), fmaxf(mpart[2*TT+t], mpart[3*TT+t]));
    }
    __syncthreads();
    float mt = ms[t];

    float a0[8];
    float a1[8];
    #pragma unroll
    for (int j = 0; j < 8; j++) {
        a0[j] = 0.f;
        a1[j] = 0.f;
    }
    float zloc = 0.f;
    int t0 = tid >> 3;
    const float4* Y = (const float4*)g_yh;

    for (int c0 = r0; c0 < r1; c0 += CH) {
        int cn = min(CH, r1 - c0);
        if (tid < cn) {
            srcs[tid] = g_csr_src[c0+tid];
            ws[tid] = g_csr_w[c0+tid];
        }
        __syncthreads();
        #pragma unroll
        for (int k = 0; k < 4; k++) {
            int ee = q + 4*k;
            if (ee < cn) {
                int s = srcs[ee];
                float a = g_p[s*TT + t] + qvt;
                a = a > 0.f ? a : 0.2f*a;
                float cc = __expf(a - mt);
                zloc += cc;
                coefw[ee*TT + t] = cc * ws[ee];
            }
        }
        __syncthreads();
        for (int ee = 0; ee < cn; ee++) {
            const float4* ys = Y + (size_t)srcs[ee]*512;
            float4 v0 = ys[tid];
            float4 v1 = ys[tid + 256];
            float c0f = coefw[ee*TT + t0];
            float c1f = coefw[ee*TT + t0 + 32];
            const __half2* p0 = (const __half2*)&v0;
            const __half2* p1 = (const __half2*)&v1;
            #pragma unroll
            for (int j = 0; j < 4; j++) {
                float2 f0 = __half22float2(p0[j]);
                a0[2*j]   += c0f*f0.x;
                a0[2*j+1] += c0f*f0.y;
                float2 f1 = __half22float2(p1[j]);
                a1[2*j]   += c1f*f1.x;
                a1[2*j+1] += c1f*f1.y;
            }
        }
        __syncthreads();
    }

    zpart[q*TT + t] = zloc;
    __syncthreads();
    if (tid < TT) {
        float z = zpart[t] + zpart[TT+t] + zpart[2*TT+t] + zpart[3*TT+t];
        zinv[t] = 1.f/(z + 1e-16f);
    }
    __syncthreads();

    if (deg > 0) {
        float4* O4 = (float4*)(out + (size_t)d*TT*HH);
        float i0v = zinv[t0];
        float i1v = zinv[t0+32];
        float4 o;
        o = O4[tid*2];
        o.x += a0[0]*i0v; o.y += a0[1]*i0v; o.z += a0[2]*i0v; o.w += a0[3]*i0v;
        O4[tid*2] = o;
        o = O4[tid*2+1];
        o.x += a0[4]*i0v; o.y += a0[5]*i0v; o.z += a0[6]*i0v; o.w += a0[7]*i0v;
        O4[tid*2+1] = o;
        o = O4[(tid+256)*2];
        o.x += a1[0]*i1v; o.y += a1[1]*i1v; o.z += a1[2]*i1v; o.w += a1[3]*i1v;
        O4[(tid+256)*2] = o;
        o = O4[(tid+256)*2+1];
        o.x += a1[4]*i1v; o.y += a1[5]*i1v; o.z += a1[6]*i1v; o.w += a1[7]*i1v;
        O4[(tid+256)*2+1] = o;
    }
}

// ---------------- launch ----------------
extern "C" void kernel_launch(void* const* d_in, const int* in_sizes, int n_in,
                              void* d_out, int out_size) {
    const float* x   = (const float*)d_in[0];
    const int*   fei = (const int*)  d_in[1];
    const float* fea = (const float*)d_in[2];
    const float* npw = (const float*)d_in[3];
    const float* ml  = (const float*)d_in[4];
    const float* tw  = (const float*)d_in[5];
    const float* tb  = (const float*)d_in[6];
    const float* lmw = (const float*)d_in[7];
    const float* lmb = (const float*)d_in[8];
    const float* lsw = (const float*)d_in[9];
    const float* lsb = (const float*)d_in[10];
    const float* asw = (const float*)d_in[11];
    const float* asb = (const float*)d_in[12];
    const float* adw = (const float*)d_in[13];
    const float* adb = (const float*)d_in[14];
    float* out = (float*)d_out;

    cudaFuncSetAttribute(k_node, cudaFuncAttributeMaxDynamicSharedMemorySize, SM_BYTES);
    cudaFuncSetAttribute(k_topk, cudaFuncAttributeMaxDynamicSharedMemorySize, TK_SM_BYTES);

    k_prep   <<<HH+1, 192>>>(tw, tb, lmw, lmb, asw, asb, adw, adb, lsw);
    k_embed  <<<NN, 64>>>(x, npw);
    k_topk   <<<NN/RPB, 256, TK_SM_BYTES>>>(ml, fei);
    k_node   <<<NN, 256, SM_BYTES>>>(x, lsb, out);
    k_scan   <<<1, 1024>>>();
    k_scatter<<<(EE+255)/256, 256>>>(fei, fea, ml);
    k_aggr   <<<NN, 256>>>(out);
}